// round 1
// baseline (speedup 1.0000x reference)
#include <cuda_runtime.h>
#include <math.h>

// Problem constants
#define Bb   2
#define Ss   2048
#define Dd   512
#define Hh   8
#define DHh  64
#define DHID 1024
#define NBLK 12
#define MTOT (Bb * Ss)      // 4096 rows

// ---------------------------------------------------------------------------
// Scratch (device globals; no allocation allowed)
// ---------------------------------------------------------------------------
__device__ float g_x  [MTOT * Dd];        // running activation
__device__ float g_xn [MTOT * Dd];        // LN1 output
__device__ float g_qkv[MTOT * 3 * Dd];    // qkv projections
__device__ float g_att[MTOT * Dd];        // attention output (merged heads)
__device__ float g_h1 [MTOT * DHID];      // MLP hidden

// ---------------------------------------------------------------------------
// GEMM: C[M,N] = A[M,K] @ W[K,N] + bias (+ residual) (+ relu)
// M = 4096 fixed. BM=128, BN=64, BK=16, 256 threads, 8x4 per thread.
// ---------------------------------------------------------------------------
#define FLAG_RES  1
#define FLAG_RELU 2

template <int FLAGS>
__global__ __launch_bounds__(256) void gemm_kernel(
    const float* __restrict__ A, const float* __restrict__ W,
    const float* __restrict__ bias, const float* __restrict__ R,
    float* __restrict__ C, int K, int N)
{
    __shared__ float As[16 * 132];   // [k][m], pitch 132
    __shared__ float Bs[16 * 64];    // [k][n], pitch 64

    const int t  = threadIdx.x;
    const int tx = t & 15;           // 0..15 -> 4 cols
    const int ty = t >> 4;           // 0..15 -> 8 rows
    const int row0 = blockIdx.y * 128;
    const int col0 = blockIdx.x * 64;

    float acc[8][4];
#pragma unroll
    for (int i = 0; i < 8; i++)
#pragma unroll
        for (int j = 0; j < 4; j++) acc[i][j] = 0.f;

    for (int kt = 0; kt < K; kt += 16) {
        // Load A tile 128x16 (2 float4 per thread), store transposed As[k][m]
#pragma unroll
        for (int i = 0; i < 2; i++) {
            int f  = t + i * 256;            // 0..511 float4 units
            int r  = f >> 2;                 // row in tile 0..127
            int kq = (f & 3) * 4;            // k offset 0,4,8,12
            float4 v = *(const float4*)(A + (size_t)(row0 + r) * K + kt + kq);
            As[(kq + 0) * 132 + r] = v.x;
            As[(kq + 1) * 132 + r] = v.y;
            As[(kq + 2) * 132 + r] = v.z;
            As[(kq + 3) * 132 + r] = v.w;
        }
        // Load B tile 16x64 (1 float4 per thread), direct
        {
            int kr = t >> 4;                 // 0..15
            int c  = (t & 15) * 4;           // 0..60
            float4 v = *(const float4*)(W + (size_t)(kt + kr) * N + col0 + c);
            *(float4*)&Bs[kr * 64 + c] = v;
        }
        __syncthreads();

#pragma unroll
        for (int k = 0; k < 16; k++) {
            float4 a0 = *(const float4*)&As[k * 132 + ty * 8];
            float4 a1 = *(const float4*)&As[k * 132 + ty * 8 + 4];
            float4 b0 = *(const float4*)&Bs[k * 64 + tx * 4];
            float a[8] = {a0.x, a0.y, a0.z, a0.w, a1.x, a1.y, a1.z, a1.w};
            float bb[4] = {b0.x, b0.y, b0.z, b0.w};
#pragma unroll
            for (int i = 0; i < 8; i++)
#pragma unroll
                for (int j = 0; j < 4; j++)
                    acc[i][j] = fmaf(a[i], bb[j], acc[i][j]);
        }
        __syncthreads();
    }

    // Epilogue
    float4 b4 = *(const float4*)(bias + col0 + tx * 4);
#pragma unroll
    for (int i = 0; i < 8; i++) {
        int row = row0 + ty * 8 + i;
        float4 v;
        v.x = acc[i][0] + b4.x;
        v.y = acc[i][1] + b4.y;
        v.z = acc[i][2] + b4.z;
        v.w = acc[i][3] + b4.w;
        if (FLAGS & FLAG_RES) {
            float4 r4 = *(const float4*)(R + (size_t)row * N + col0 + tx * 4);
            v.x += r4.x; v.y += r4.y; v.z += r4.z; v.w += r4.w;
        }
        if (FLAGS & FLAG_RELU) {
            v.x = fmaxf(v.x, 0.f); v.y = fmaxf(v.y, 0.f);
            v.z = fmaxf(v.z, 0.f); v.w = fmaxf(v.w, 0.f);
        }
        *(float4*)(C + (size_t)row * N + col0 + tx * 4) = v;
    }
}

// ---------------------------------------------------------------------------
// Fused flash attention, fp32. Grid: (S/64, H, B). 256 threads.
// qkv layout: [b, s, h*192 + {0:q, 64:k, 128:v} + d]. Output [b, s, h*64+d].
// scale = 1/sqrt(D) = 1/sqrt(512)  (reference quirk: d_model, not d_head)
// smem: Qs 64x64 | Ks 64x68 (reused for P) | Vs 64x64 -> 50176 B dynamic
// ---------------------------------------------------------------------------
#define ATTN_SMEM ((64 * 64 + 64 * 68 + 64 * 64) * 4)

__global__ __launch_bounds__(256) void attn_kernel(
    const float* __restrict__ qkv, float* __restrict__ out)
{
    extern __shared__ float sm[];
    float* Qs = sm;                     // pitch 64
    float* Ks = sm + 64 * 64;           // pitch 68 (also P)
    float* Vs = sm + 64 * 64 + 64 * 68; // pitch 64

    const int t  = threadIdx.x;
    const int tx = t & 15;              // col group
    const int ty = t >> 4;              // row group (4 rows)
    const int h  = blockIdx.y;
    const int b  = blockIdx.z;
    const int q0 = blockIdx.x * 64;
    const float scale = 0.04419417382415922f;   // 1/sqrt(512)

    const float* base = qkv + (size_t)b * Ss * (3 * Dd) + h * (3 * DHh);

    // Load Q tile (rows q0..q0+63, d 0..63)
#pragma unroll
    for (int i = 0; i < 4; i++) {
        int f  = t + i * 256;
        int r  = f >> 4;
        int dv = (f & 15) * 4;
        float4 v = *(const float4*)(base + (size_t)(q0 + r) * (3 * Dd) + dv);
        Qs[r * 64 + dv + 0] = v.x;
        Qs[r * 64 + dv + 1] = v.y;
        Qs[r * 64 + dv + 2] = v.z;
        Qs[r * 64 + dv + 3] = v.w;
    }

    float o[4][4];
    float m[4], l[4];
#pragma unroll
    for (int i = 0; i < 4; i++) {
        m[i] = -1e30f; l[i] = 0.f;
#pragma unroll
        for (int j = 0; j < 4; j++) o[i][j] = 0.f;
    }

    for (int kt = 0; kt < Ss / 64; kt++) {
        __syncthreads();   // Q ready (iter 0) / prior O-gemm done with Ks,Vs

        // Load K and V tiles (64 kv rows x 64 d)
#pragma unroll
        for (int i = 0; i < 4; i++) {
            int f  = t + i * 256;
            int r  = f >> 4;
            int dv = (f & 15) * 4;
            const float* rowp = base + (size_t)(kt * 64 + r) * (3 * Dd) + dv;
            float4 kv = *(const float4*)(rowp + 64);
            float4 vv = *(const float4*)(rowp + 128);
            Ks[r * 68 + dv + 0] = kv.x;
            Ks[r * 68 + dv + 1] = kv.y;
            Ks[r * 68 + dv + 2] = kv.z;
            Ks[r * 68 + dv + 3] = kv.w;
            Vs[r * 64 + dv + 0] = vv.x;
            Vs[r * 64 + dv + 1] = vv.y;
            Vs[r * 64 + dv + 2] = vv.z;
            Vs[r * 64 + dv + 3] = vv.w;
        }
        __syncthreads();

        // S = Q K^T  (thread: rows ty*4+i, cols tx+16j)
        float s[4][4];
#pragma unroll
        for (int i = 0; i < 4; i++)
#pragma unroll
            for (int j = 0; j < 4; j++) s[i][j] = 0.f;

#pragma unroll
        for (int kb = 0; kb < 16; kb++) {
            float4 q4[4], k4[4];
#pragma unroll
            for (int i = 0; i < 4; i++)
                q4[i] = *(const float4*)&Qs[(ty * 4 + i) * 64 + kb * 4];
#pragma unroll
            for (int j = 0; j < 4; j++)
                k4[j] = *(const float4*)&Ks[(tx + 16 * j) * 68 + kb * 4];
#pragma unroll
            for (int i = 0; i < 4; i++)
#pragma unroll
                for (int j = 0; j < 4; j++) {
                    s[i][j] = fmaf(q4[i].x, k4[j].x, s[i][j]);
                    s[i][j] = fmaf(q4[i].y, k4[j].y, s[i][j]);
                    s[i][j] = fmaf(q4[i].z, k4[j].z, s[i][j]);
                    s[i][j] = fmaf(q4[i].w, k4[j].w, s[i][j]);
                }
        }

        // Online softmax update (row groups share 16 lanes -> shfl width 16)
#pragma unroll
        for (int i = 0; i < 4; i++) {
#pragma unroll
            for (int j = 0; j < 4; j++) s[i][j] *= scale;
            float mt = fmaxf(fmaxf(s[i][0], s[i][1]), fmaxf(s[i][2], s[i][3]));
#pragma unroll
            for (int off = 8; off > 0; off >>= 1)
                mt = fmaxf(mt, __shfl_xor_sync(0xffffffffu, mt, off, 16));
            float mn   = fmaxf(m[i], mt);
            float corr = __expf(m[i] - mn);
            m[i] = mn;
            float rs = 0.f;
#pragma unroll
            for (int j = 0; j < 4; j++) {
                float p = __expf(s[i][j] - mn);
                s[i][j] = p;
                rs += p;
            }
#pragma unroll
            for (int off = 8; off > 0; off >>= 1)
                rs += __shfl_xor_sync(0xffffffffu, rs, off, 16);
            l[i] = l[i] * corr + rs;
#pragma unroll
            for (int j = 0; j < 4; j++) o[i][j] *= corr;
        }

        __syncthreads();   // all S-gemm reads of Ks done before P overwrite
#pragma unroll
        for (int i = 0; i < 4; i++)
#pragma unroll
            for (int j = 0; j < 4; j++)
                Ks[(ty * 4 + i) * 68 + tx + 16 * j] = s[i][j];
        __syncthreads();

        // O += P V  (thread: rows ty*4+i, d cols tx*4+j)
#pragma unroll
        for (int cb = 0; cb < 16; cb++) {
            float4 p4[4];
#pragma unroll
            for (int i = 0; i < 4; i++)
                p4[i] = *(const float4*)&Ks[(ty * 4 + i) * 68 + cb * 4];
            float4 v0 = *(const float4*)&Vs[(cb * 4 + 0) * 64 + tx * 4];
            float4 v1 = *(const float4*)&Vs[(cb * 4 + 1) * 64 + tx * 4];
            float4 v2 = *(const float4*)&Vs[(cb * 4 + 2) * 64 + tx * 4];
            float4 v3 = *(const float4*)&Vs[(cb * 4 + 3) * 64 + tx * 4];
#pragma unroll
            for (int i = 0; i < 4; i++) {
                o[i][0] = fmaf(p4[i].x, v0.x, o[i][0]);
                o[i][1] = fmaf(p4[i].x, v0.y, o[i][1]);
                o[i][2] = fmaf(p4[i].x, v0.z, o[i][2]);
                o[i][3] = fmaf(p4[i].x, v0.w, o[i][3]);
                o[i][0] = fmaf(p4[i].y, v1.x, o[i][0]);
                o[i][1] = fmaf(p4[i].y, v1.y, o[i][1]);
                o[i][2] = fmaf(p4[i].y, v1.z, o[i][2]);
                o[i][3] = fmaf(p4[i].y, v1.w, o[i][3]);
                o[i][0] = fmaf(p4[i].z, v2.x, o[i][0]);
                o[i][1] = fmaf(p4[i].z, v2.y, o[i][1]);
                o[i][2] = fmaf(p4[i].z, v2.z, o[i][2]);
                o[i][3] = fmaf(p4[i].z, v2.w, o[i][3]);
                o[i][0] = fmaf(p4[i].w, v3.x, o[i][0]);
                o[i][1] = fmaf(p4[i].w, v3.y, o[i][1]);
                o[i][2] = fmaf(p4[i].w, v3.z, o[i][2]);
                o[i][3] = fmaf(p4[i].w, v3.w, o[i][3]);
            }
        }
    }

    // Epilogue: out[b, q0+r, h*64 + d] = o / l
    float* op = out + ((size_t)b * Ss + q0) * Dd + h * DHh;
#pragma unroll
    for (int i = 0; i < 4; i++) {
        float inv = 1.f / l[i];
        float4 v;
        v.x = o[i][0] * inv; v.y = o[i][1] * inv;
        v.z = o[i][2] * inv; v.w = o[i][3] * inv;
        *(float4*)(op + (size_t)(ty * 4 + i) * Dd + tx * 4) = v;
    }
}

// ---------------------------------------------------------------------------
// LayerNorm over D=512. Grid: 4096 rows, 128 threads (4 floats/thread).
// ---------------------------------------------------------------------------
__global__ __launch_bounds__(128) void ln_kernel(
    const float* __restrict__ in, const float* __restrict__ g,
    const float* __restrict__ b, float* __restrict__ out)
{
    const int row = blockIdx.x;
    const int t   = threadIdx.x;

    float4 v = *(const float4*)(in + (size_t)row * Dd + t * 4);
    float s  = v.x + v.y + v.z + v.w;
    float ss = v.x * v.x + v.y * v.y + v.z * v.z + v.w * v.w;

#pragma unroll
    for (int off = 16; off > 0; off >>= 1) {
        s  += __shfl_xor_sync(0xffffffffu, s, off);
        ss += __shfl_xor_sync(0xffffffffu, ss, off);
    }
    __shared__ float sm_s[4], sm_ss[4];
    if ((t & 31) == 0) { sm_s[t >> 5] = s; sm_ss[t >> 5] = ss; }
    __syncthreads();
    s  = sm_s[0] + sm_s[1] + sm_s[2] + sm_s[3];
    ss = sm_ss[0] + sm_ss[1] + sm_ss[2] + sm_ss[3];

    const float inv_n = 1.f / (float)Dd;
    float mean = s * inv_n;
    float var  = ss * inv_n - mean * mean;
    float rstd = rsqrtf(var + 1e-5f);

    float4 g4 = *(const float4*)(g + t * 4);
    float4 b4 = *(const float4*)(b + t * 4);
    float4 r;
    r.x = (v.x - mean) * rstd * g4.x + b4.x;
    r.y = (v.y - mean) * rstd * g4.y + b4.y;
    r.z = (v.z - mean) * rstd * g4.z + b4.z;
    r.w = (v.w - mean) * rstd * g4.w + b4.w;
    *(float4*)(out + (size_t)row * Dd + t * 4) = r;
}

// ---------------------------------------------------------------------------
// Launcher
// ---------------------------------------------------------------------------
extern "C" void kernel_launch(void* const* d_in, const int* in_sizes, int n_in,
                              void* d_out, int out_size)
{
    const float* X     = (const float*)d_in[0];
    const float* qkv_w = (const float*)d_in[1];
    const float* qkv_b = (const float*)d_in[2];
    const float* fc_w  = (const float*)d_in[3];
    const float* fc_b  = (const float*)d_in[4];
    const float* ln1_g = (const float*)d_in[5];
    const float* ln1_b = (const float*)d_in[6];
    const float* w1    = (const float*)d_in[7];
    const float* b1    = (const float*)d_in[8];
    const float* w2    = (const float*)d_in[9];
    const float* b2    = (const float*)d_in[10];
    const float* ln2_g = (const float*)d_in[11];
    const float* ln2_b = (const float*)d_in[12];
    float* out = (float*)d_out;

    float *x, *xn, *qkv, *att, *h1;
    cudaGetSymbolAddress((void**)&x,   g_x);
    cudaGetSymbolAddress((void**)&xn,  g_xn);
    cudaGetSymbolAddress((void**)&qkv, g_qkv);
    cudaGetSymbolAddress((void**)&att, g_att);
    cudaGetSymbolAddress((void**)&h1,  g_h1);

    cudaFuncSetAttribute(attn_kernel,
                         cudaFuncAttributeMaxDynamicSharedMemorySize, ATTN_SMEM);

    const dim3 blk256(256);
    for (int blk = 0; blk < NBLK; blk++) {
        const float* xin = (blk == 0) ? X : x;

        // qkv = x @ qkv_w + qkv_b          [4096, 1536]
        gemm_kernel<0><<<dim3((3 * Dd) / 64, MTOT / 128), blk256>>>(
            xin, qkv_w + (size_t)blk * Dd * 3 * Dd, qkv_b + (size_t)blk * 3 * Dd,
            nullptr, qkv, Dd, 3 * Dd);

        // att = softmax(qk^T * scale) v    [4096, 512]
        attn_kernel<<<dim3(Ss / 64, Hh, Bb), blk256, ATTN_SMEM>>>(qkv, att);

        // x = xin + att @ fc_w + fc_b
        gemm_kernel<FLAG_RES><<<dim3(Dd / 64, MTOT / 128), blk256>>>(
            att, fc_w + (size_t)blk * Dd * Dd, fc_b + (size_t)blk * Dd,
            xin, x, Dd, Dd);

        // xn = ln1(x)
        ln_kernel<<<MTOT, 128>>>(x, ln1_g + (size_t)blk * Dd,
                                 ln1_b + (size_t)blk * Dd, xn);

        // h1 = relu(xn @ w1 + b1)          [4096, 1024]
        gemm_kernel<FLAG_RELU><<<dim3(DHID / 64, MTOT / 128), blk256>>>(
            xn, w1 + (size_t)blk * Dd * DHID, b1 + (size_t)blk * DHID,
            nullptr, h1, Dd, DHID);

        // x = x + h1 @ w2 + b2
        gemm_kernel<FLAG_RES><<<dim3(Dd / 64, MTOT / 128), blk256>>>(
            h1, w2 + (size_t)blk * DHID * Dd, b2 + (size_t)blk * Dd,
            x, x, DHID, Dd);

        // x = ln2(x)   (last block writes straight to d_out)
        ln_kernel<<<MTOT, 128>>>(x, ln2_g + (size_t)blk * Dd,
                                 ln2_b + (size_t)blk * Dd,
                                 (blk == NBLK - 1) ? out : x);
    }
}

// round 3
// speedup vs baseline: 2.2013x; 2.2013x over previous
#include <cuda_runtime.h>
#include <cuda_bf16.h>
#include <cstdint>
#include <math.h>

typedef __nv_bfloat16 bf16;

// Problem constants
#define Bb   2
#define Ss   2048
#define Dd   512
#define Hh   8
#define DHh  64
#define DHID 1024
#define NBLK 12
#define MTOT (Bb * Ss)      // 4096 rows

#define FLAG_RES  1
#define FLAG_RELU 2
#define FLAG_OUTB 4

// ---------------------------------------------------------------------------
// Scratch (device globals)
// ---------------------------------------------------------------------------
__device__ float g_x  [MTOT * Dd];
__device__ float g_xn [MTOT * Dd];
__device__ float g_qkv[MTOT * 3 * Dd];
__device__ float g_att[MTOT * Dd];

__device__ bf16 g_Xh [MTOT * Dd];
__device__ bf16 g_Xl [MTOT * Dd];
__device__ bf16 g_xh [MTOT * Dd];
__device__ bf16 g_xl [MTOT * Dd];
__device__ bf16 g_xnh[MTOT * Dd];
__device__ bf16 g_xnl[MTOT * Dd];
__device__ bf16 g_ath[MTOT * Dd];
__device__ bf16 g_atl[MTOT * Dd];
__device__ bf16 g_h1h[MTOT * DHID];
__device__ bf16 g_h1l[MTOT * DHID];

// Transposed + bf16-split weights: [blk][N][K]
__device__ bf16 g_qkvwTh[NBLK * 1536 * 512];
__device__ bf16 g_qkvwTl[NBLK * 1536 * 512];
__device__ bf16 g_fcwTh [NBLK * 512 * 512];
__device__ bf16 g_fcwTl [NBLK * 512 * 512];
__device__ bf16 g_w1Th  [NBLK * 1024 * 512];
__device__ bf16 g_w1Tl  [NBLK * 1024 * 512];
__device__ bf16 g_w2Th  [NBLK * 512 * 1024];
__device__ bf16 g_w2Tl  [NBLK * 512 * 1024];

// ---------------------------------------------------------------------------
// PTX helpers (all baseline sm_80+ features; compile for compute_100)
// ---------------------------------------------------------------------------
__device__ __forceinline__ uint32_t smem_u32(const void* p) {
    uint32_t a;
    asm("{ .reg .u64 t; cvta.to.shared.u64 t, %1; cvt.u32.u64 %0, t; }"
        : "=r"(a) : "l"(p));
    return a;
}
__device__ __forceinline__ void cpa16(uint32_t s, const void* g) {
    asm volatile("cp.async.ca.shared.global [%0], [%1], 16;" :: "r"(s), "l"(g));
}
__device__ __forceinline__ void cp_commit() {
    asm volatile("cp.async.commit_group;" ::: "memory");
}
__device__ __forceinline__ void cp_wait1() {
    asm volatile("cp.async.wait_group 1;" ::: "memory");
}
__device__ __forceinline__ void cp_wait0() {
    asm volatile("cp.async.wait_group 0;" ::: "memory");
}
__device__ __forceinline__ void ldsm4(uint32_t a[4], uint32_t addr) {
    asm volatile("ldmatrix.sync.aligned.m8n8.x4.shared.b16 {%0,%1,%2,%3}, [%4];"
                 : "=r"(a[0]), "=r"(a[1]), "=r"(a[2]), "=r"(a[3]) : "r"(addr));
}
__device__ __forceinline__ void mma_bf16(float c[4], const uint32_t a[4],
                                         const uint32_t b[2]) {
    asm volatile(
        "mma.sync.aligned.m16n8k16.row.col.f32.bf16.bf16.f32 "
        "{%0,%1,%2,%3}, {%4,%5,%6,%7}, {%8,%9}, {%0,%1,%2,%3};"
        : "+f"(c[0]), "+f"(c[1]), "+f"(c[2]), "+f"(c[3])
        : "r"(a[0]), "r"(a[1]), "r"(a[2]), "r"(a[3]), "r"(b[0]), "r"(b[1]));
}
__device__ __forceinline__ void mma_tf32(float c[4], const uint32_t a[4],
                                         const uint32_t b[2]) {
    asm volatile(
        "mma.sync.aligned.m16n8k8.row.col.f32.tf32.tf32.f32 "
        "{%0,%1,%2,%3}, {%4,%5,%6,%7}, {%8,%9}, {%0,%1,%2,%3};"
        : "+f"(c[0]), "+f"(c[1]), "+f"(c[2]), "+f"(c[3])
        : "r"(a[0]), "r"(a[1]), "r"(a[2]), "r"(a[3]), "r"(b[0]), "r"(b[1]));
}
__device__ __forceinline__ float to_tf32(float x) {
    uint32_t u;
    asm("cvt.rna.tf32.f32 %0, %1;" : "=r"(u) : "f"(x));
    return __uint_as_float(u);
}
__device__ __forceinline__ uint32_t packbf(float lo, float hi) {
    uint32_t u;
    asm("cvt.rn.bf16x2.f32 %0, %1, %2;" : "=r"(u) : "f"(hi), "f"(lo));
    return u;
}
// split pair into bf16 hi-pair and lo-pair (packed)
__device__ __forceinline__ void split2(float a, float b, uint32_t& hp, uint32_t& lp) {
    float ha = __bfloat162float(__float2bfloat16(a));
    float hb = __bfloat162float(__float2bfloat16(b));
    hp = packbf(ha, hb);
    lp = packbf(a - ha, b - hb);
}

// ---------------------------------------------------------------------------
// Weight transpose + bf16 split: W[K,N] -> Th/Tl[N,K] bf16, per blockIdx.z
// ---------------------------------------------------------------------------
__global__ __launch_bounds__(256) void transpose_split_kernel(
    const float* __restrict__ W, bf16* __restrict__ Th, bf16* __restrict__ Tl,
    int K, int N)
{
    __shared__ float ts[32][33];
    const int z = blockIdx.z;
    W  += (size_t)z * K * N;
    Th += (size_t)z * N * K;
    Tl += (size_t)z * N * K;
    const int n0 = blockIdx.x * 32, k0 = blockIdx.y * 32;
    const int tx = threadIdx.x, ty = threadIdx.y;   // (32, 8)
#pragma unroll
    for (int i = 0; i < 4; i++)
        ts[ty + i * 8][tx] = W[(size_t)(k0 + ty + i * 8) * N + n0 + tx];
    __syncthreads();
#pragma unroll
    for (int i = 0; i < 4; i++) {
        float v = ts[tx][ty + i * 8];
        bf16 h = __float2bfloat16(v);
        size_t o = (size_t)(n0 + ty + i * 8) * K + k0 + tx;
        Th[o] = h;
        Tl[o] = __float2bfloat16(v - __bfloat162float(h));
    }
}

// X -> bf16 hi/lo split (elementwise)
__global__ __launch_bounds__(256) void convert_split_kernel(
    const float* __restrict__ in, bf16* __restrict__ h, bf16* __restrict__ l, int n)
{
    int i = (blockIdx.x * 256 + threadIdx.x) * 4;
    if (i >= n) return;
    float4 v = *(const float4*)(in + i);
    uint32_t h0, l0, h1, l1;
    split2(v.x, v.y, h0, l0);
    split2(v.z, v.w, h1, l1);
    uint2 hp = make_uint2(h0, h1), lp = make_uint2(l0, l1);
    *(uint2*)(h + i) = hp;
    *(uint2*)(l + i) = lp;
}

// ---------------------------------------------------------------------------
// bf16 3x-split GEMM via mma.sync: C[M,N] = A @ W^T + bias (+res)(+relu)
// A: bf16 hi/lo [M][K]; B: bf16 hi/lo [N][K]. CTA 128x128, BK=32, 8 warps.
// smem: 2 buffers x {AsH, AsL, BsH, BsL}[128][40] bf16  (pitch 80B, conflict-free)
// ---------------------------------------------------------------------------
#define GEMM_SMEM (2 * 4 * 128 * 40 * 2)   // 81920 B

template <int FLAGS>
__global__ __launch_bounds__(256, 1) void gemm_mma(
    const bf16* __restrict__ Ah, const bf16* __restrict__ Al,
    const bf16* __restrict__ Bh, const bf16* __restrict__ Bl,
    const float* __restrict__ bias, const float* __restrict__ R,
    float* __restrict__ C, bf16* __restrict__ Ch, bf16* __restrict__ Cl,
    int K, int N)
{
    extern __shared__ char smraw[];
    const uint32_t sb = smem_u32(smraw);
    const int t = threadIdx.x, lane = t & 31, wid = t >> 5;
    const int row0 = blockIdx.y * 128, col0 = blockIdx.x * 128;
    const int m0 = (wid >> 2) * 64, n0 = (wid & 3) * 32;
    const int NI = K >> 5;

    const int r = t >> 1, hf = t & 1;
    const bf16* gAh = Ah + (size_t)(row0 + r) * K + hf * 16;
    const bf16* gAl = Al + (size_t)(row0 + r) * K + hf * 16;
    const bf16* gBh = Bh + (size_t)(col0 + r) * K + hf * 16;
    const bf16* gBl = Bl + (size_t)(col0 + r) * K + hf * 16;
    const uint32_t sOff = (uint32_t)(r * 80 + hf * 32);

    float acc[4][4][4];
#pragma unroll
    for (int a = 0; a < 4; a++)
#pragma unroll
        for (int b = 0; b < 4; b++)
#pragma unroll
            for (int c = 0; c < 4; c++) acc[a][b][c] = 0.f;

#define ISSUE(i) do {                                            \
    uint32_t bo = sb + (uint32_t)((i) & 1) * 40960u + sOff;      \
    const bf16* pa = gAh + (size_t)(i) * 32;                     \
    const bf16* pl = gAl + (size_t)(i) * 32;                     \
    const bf16* pb = gBh + (size_t)(i) * 32;                     \
    const bf16* pc = gBl + (size_t)(i) * 32;                     \
    cpa16(bo,              pa); cpa16(bo + 16,         pa + 8);  \
    cpa16(bo + 10240,      pl); cpa16(bo + 10240 + 16, pl + 8);  \
    cpa16(bo + 20480,      pb); cpa16(bo + 20480 + 16, pb + 8);  \
    cpa16(bo + 30720,      pc); cpa16(bo + 30720 + 16, pc + 8);  \
    cp_commit(); } while (0)

    ISSUE(0);
    for (int i = 0; i < NI; i++) {
        if (i + 1 < NI) { ISSUE(i + 1); cp_wait1(); }
        else cp_wait0();
        __syncthreads();
        const uint32_t bufb = sb + (uint32_t)(i & 1) * 40960u;
#pragma unroll
        for (int ks = 0; ks < 2; ks++) {
            const int kb = ks * 16;
            uint32_t ah[4][4], alr[4][4], bh[4][2], bl2[4][2];
#pragma unroll
            for (int mi = 0; mi < 4; mi++) {
                uint32_t ad = bufb + (uint32_t)(((m0 + mi * 16 + (lane & 15)) * 40
                                                + kb + (lane >> 4) * 8) * 2);
                ldsm4(ah[mi], ad);
                ldsm4(alr[mi], ad + 10240);
            }
            {
                const int l8 = lane & 7, q = lane >> 3;
                uint32_t bd = bufb + 20480 + (uint32_t)(((n0 + (q >> 1) * 8 + l8) * 40
                                                        + kb + (q & 1) * 8) * 2);
                uint32_t tmp[4];
                ldsm4(tmp, bd);
                bh[0][0] = tmp[0]; bh[0][1] = tmp[1]; bh[1][0] = tmp[2]; bh[1][1] = tmp[3];
                ldsm4(tmp, bd + 10240);
                bl2[0][0] = tmp[0]; bl2[0][1] = tmp[1]; bl2[1][0] = tmp[2]; bl2[1][1] = tmp[3];
                uint32_t bd2 = bd + 16 * 80;
                ldsm4(tmp, bd2);
                bh[2][0] = tmp[0]; bh[2][1] = tmp[1]; bh[3][0] = tmp[2]; bh[3][1] = tmp[3];
                ldsm4(tmp, bd2 + 10240);
                bl2[2][0] = tmp[0]; bl2[2][1] = tmp[1]; bl2[3][0] = tmp[2]; bl2[3][1] = tmp[3];
            }
#pragma unroll
            for (int mi = 0; mi < 4; mi++)
#pragma unroll
                for (int ni = 0; ni < 4; ni++) {
                    mma_bf16(acc[mi][ni], ah[mi],  bh[ni]);
                    mma_bf16(acc[mi][ni], alr[mi], bh[ni]);
                    mma_bf16(acc[mi][ni], ah[mi],  bl2[ni]);
                }
        }
        __syncthreads();
    }
#undef ISSUE

    // Epilogue
    const int gid = lane >> 2, tig = lane & 3;
#pragma unroll
    for (int mi = 0; mi < 4; mi++) {
        const int ra = row0 + m0 + mi * 16 + gid;
#pragma unroll
        for (int ni = 0; ni < 4; ni++) {
            const int col = col0 + n0 + ni * 8 + tig * 2;
            float2 bv = *(const float2*)(bias + col);
            float x0 = acc[mi][ni][0] + bv.x, x1 = acc[mi][ni][1] + bv.y;
            float x2 = acc[mi][ni][2] + bv.x, x3 = acc[mi][ni][3] + bv.y;
            if (FLAGS & FLAG_RES) {
                float2 r0 = *(const float2*)(R + (size_t)ra * N + col);
                float2 r1 = *(const float2*)(R + (size_t)(ra + 8) * N + col);
                x0 += r0.x; x1 += r0.y; x2 += r1.x; x3 += r1.y;
            }
            if (FLAGS & FLAG_RELU) {
                x0 = fmaxf(x0, 0.f); x1 = fmaxf(x1, 0.f);
                x2 = fmaxf(x2, 0.f); x3 = fmaxf(x3, 0.f);
            }
            if (FLAGS & FLAG_OUTB) {
                uint32_t hp, lp;
                split2(x0, x1, hp, lp);
                *(uint32_t*)(Ch + (size_t)ra * N + col) = hp;
                *(uint32_t*)(Cl + (size_t)ra * N + col) = lp;
                split2(x2, x3, hp, lp);
                *(uint32_t*)(Ch + (size_t)(ra + 8) * N + col) = hp;
                *(uint32_t*)(Cl + (size_t)(ra + 8) * N + col) = lp;
            } else {
                float2 o0 = make_float2(x0, x1), o1 = make_float2(x2, x3);
                *(float2*)(C + (size_t)ra * N + col) = o0;
                *(float2*)(C + (size_t)(ra + 8) * N + col) = o1;
            }
        }
    }
}

// ---------------------------------------------------------------------------
// Flash attention, tf32 mma.sync. Grid (S/128, H, B), 128 threads (4 warps).
// Each warp: 32 q rows. kv tiles of 64. Online softmax in fp32 regs.
// smem floats: Qs[128][68] | Ks[64][68] | Vs[64][68] | Ps[128][68]
// ---------------------------------------------------------------------------
#define ATT_SMEM ((128 * 68 + 64 * 68 + 64 * 68 + 128 * 68) * 4)   // 104448

__global__ __launch_bounds__(128, 2) void attn_tc(
    const float* __restrict__ qkv, float* __restrict__ att,
    bf16* __restrict__ atth, bf16* __restrict__ attl)
{
    extern __shared__ float sf[];
    float* Qs = sf;                       // pitch 68
    float* Ks = sf + 128 * 68;
    float* Vs = Ks + 64 * 68;
    float* Ps = Vs + 64 * 68;

    const int t = threadIdx.x, lane = t & 31, wid = t >> 5;
    const int gid = lane >> 2, tig = lane & 3;
    const int q0 = blockIdx.x * 128, h = blockIdx.y, b = blockIdx.z;
    const int m0 = wid * 32;
    const float scale = 0.04419417382415922f;   // 1/sqrt(512)
    const float* base = qkv + (size_t)b * Ss * 1536 + h * 192;

    // Load Q (one row per thread), tf32-rounded
    {
        const float* qp = base + (size_t)(q0 + t) * 1536;
        float* qs = Qs + t * 68;
#pragma unroll
        for (int c = 0; c < 16; c++) {
            float4 v = *(const float4*)(qp + c * 4);
            qs[c * 4 + 0] = to_tf32(v.x);
            qs[c * 4 + 1] = to_tf32(v.y);
            qs[c * 4 + 2] = to_tf32(v.z);
            qs[c * 4 + 3] = to_tf32(v.w);
        }
    }

    float o[2][8][4];
#pragma unroll
    for (int a = 0; a < 2; a++)
#pragma unroll
        for (int c = 0; c < 8; c++)
#pragma unroll
            for (int d = 0; d < 4; d++) o[a][c][d] = 0.f;
    float mrow[4] = {-1e30f, -1e30f, -1e30f, -1e30f};
    float lrow[4] = {0.f, 0.f, 0.f, 0.f};

    const int r = t >> 1, hf = t & 1;

    for (int kt = 0; kt < Ss / 64; kt++) {
        __syncthreads();
        // Load K, V tiles (tf32-rounded)
        {
            const float* kp = base + (size_t)(kt * 64 + r) * 1536 + 64 + hf * 32;
            const float* vp = kp + 64;
            float* ks = Ks + r * 68 + hf * 32;
            float* vs = Vs + r * 68 + hf * 32;
#pragma unroll
            for (int c = 0; c < 8; c++) {
                float4 kv = *(const float4*)(kp + c * 4);
                float4 vv = *(const float4*)(vp + c * 4);
                ks[c * 4 + 0] = to_tf32(kv.x); ks[c * 4 + 1] = to_tf32(kv.y);
                ks[c * 4 + 2] = to_tf32(kv.z); ks[c * 4 + 3] = to_tf32(kv.w);
                vs[c * 4 + 0] = to_tf32(vv.x); vs[c * 4 + 1] = to_tf32(vv.y);
                vs[c * 4 + 2] = to_tf32(vv.z); vs[c * 4 + 3] = to_tf32(vv.w);
            }
        }
        __syncthreads();

        // S = Q K^T
        float sc[2][8][4];
#pragma unroll
        for (int a = 0; a < 2; a++)
#pragma unroll
            for (int c = 0; c < 8; c++)
#pragma unroll
                for (int d = 0; d < 4; d++) sc[a][c][d] = 0.f;

#pragma unroll
        for (int ks = 0; ks < 8; ks++) {
            uint32_t qa[2][4];
#pragma unroll
            for (int mi = 0; mi < 2; mi++) {
                const float* qr0 = Qs + (m0 + mi * 16 + gid) * 68 + ks * 8 + tig;
                const float* qr1 = qr0 + 8 * 68;
                qa[mi][0] = __float_as_uint(qr0[0]);
                qa[mi][1] = __float_as_uint(qr1[0]);
                qa[mi][2] = __float_as_uint(qr0[4]);
                qa[mi][3] = __float_as_uint(qr1[4]);
            }
#pragma unroll
            for (int ni = 0; ni < 8; ni++) {
                uint32_t kb[2];
                const float* kr = Ks + (ni * 8 + gid) * 68 + ks * 8 + tig;
                kb[0] = __float_as_uint(kr[0]);
                kb[1] = __float_as_uint(kr[4]);
#pragma unroll
                for (int mi = 0; mi < 2; mi++) mma_tf32(sc[mi][ni], qa[mi], kb);
            }
        }

        // scale
#pragma unroll
        for (int a = 0; a < 2; a++)
#pragma unroll
            for (int c = 0; c < 8; c++)
#pragma unroll
                for (int d = 0; d < 4; d++) sc[a][c][d] *= scale;

        // online softmax (4 row-slots per thread; 4-lane groups share rows)
#pragma unroll
        for (int slot = 0; slot < 4; slot++) {
            const int mi = slot >> 1, hh = slot & 1;
            float mx = -1e30f;
#pragma unroll
            for (int ni = 0; ni < 8; ni++)
                mx = fmaxf(mx, fmaxf(sc[mi][ni][hh * 2], sc[mi][ni][hh * 2 + 1]));
            mx = fmaxf(mx, __shfl_xor_sync(0xffffffffu, mx, 1));
            mx = fmaxf(mx, __shfl_xor_sync(0xffffffffu, mx, 2));
            float mn = fmaxf(mrow[slot], mx);
            float corr = __expf(mrow[slot] - mn);
            mrow[slot] = mn;
            float rs = 0.f;
#pragma unroll
            for (int ni = 0; ni < 8; ni++) {
                float p0 = __expf(sc[mi][ni][hh * 2] - mn);
                float p1 = __expf(sc[mi][ni][hh * 2 + 1] - mn);
                sc[mi][ni][hh * 2] = p0;
                sc[mi][ni][hh * 2 + 1] = p1;
                rs += p0 + p1;
            }
            rs += __shfl_xor_sync(0xffffffffu, rs, 1);
            rs += __shfl_xor_sync(0xffffffffu, rs, 2);
            lrow[slot] = lrow[slot] * corr + rs;
#pragma unroll
            for (int ni = 0; ni < 8; ni++) {
                o[mi][ni][hh * 2] *= corr;
                o[mi][ni][hh * 2 + 1] *= corr;
            }
        }

        // write P (tf32-rounded) to per-warp region of Ps
#pragma unroll
        for (int mi = 0; mi < 2; mi++) {
            const int rr = m0 + mi * 16 + gid;
#pragma unroll
            for (int ni = 0; ni < 8; ni++) {
                float2 p0 = make_float2(to_tf32(sc[mi][ni][0]), to_tf32(sc[mi][ni][1]));
                float2 p1 = make_float2(to_tf32(sc[mi][ni][2]), to_tf32(sc[mi][ni][3]));
                *(float2*)(Ps + rr * 68 + ni * 8 + tig * 2) = p0;
                *(float2*)(Ps + (rr + 8) * 68 + ni * 8 + tig * 2) = p1;
            }
        }
        __syncwarp();

        // O += P V
#pragma unroll
        for (int ks = 0; ks < 8; ks++) {
            uint32_t pa[2][4];
#pragma unroll
            for (int mi = 0; mi < 2; mi++) {
                const float* pr0 = Ps + (m0 + mi * 16 + gid) * 68 + ks * 8 + tig;
                const float* pr1 = pr0 + 8 * 68;
                pa[mi][0] = __float_as_uint(pr0[0]);
                pa[mi][1] = __float_as_uint(pr1[0]);
                pa[mi][2] = __float_as_uint(pr0[4]);
                pa[mi][3] = __float_as_uint(pr1[4]);
            }
#pragma unroll
            for (int ni = 0; ni < 8; ni++) {
                uint32_t vb[2];
                vb[0] = __float_as_uint(Vs[(ks * 8 + tig) * 68 + ni * 8 + gid]);
                vb[1] = __float_as_uint(Vs[(ks * 8 + tig + 4) * 68 + ni * 8 + gid]);
#pragma unroll
                for (int mi = 0; mi < 2; mi++) mma_tf32(o[mi][ni], pa[mi], vb);
            }
        }
    }

    // Epilogue: out[b, q0+row, h*64+col] = o / l ; plus bf16 hi/lo split
    float* ob = att + ((size_t)b * Ss + q0) * Dd + h * DHh;
#pragma unroll
    for (int slot = 0; slot < 4; slot++) {
        const int mi = slot >> 1, hh = slot & 1;
        const int row = m0 + mi * 16 + gid + hh * 8;
        const float inv = 1.f / lrow[slot];
        const size_t gb = ((size_t)b * Ss + q0 + row) * Dd + h * DHh;
#pragma unroll
        for (int ni = 0; ni < 8; ni++) {
            const int col = ni * 8 + tig * 2;
            float x0 = o[mi][ni][hh * 2] * inv;
            float x1 = o[mi][ni][hh * 2 + 1] * inv;
            *(float2*)(ob + (size_t)row * Dd + col) = make_float2(x0, x1);
            uint32_t hp, lp;
            split2(x0, x1, hp, lp);
            *(uint32_t*)(atth + gb + col) = hp;
            *(uint32_t*)(attl + gb + col) = lp;
        }
    }
}

// ---------------------------------------------------------------------------
// LayerNorm over D=512 + bf16 hi/lo split outputs
// ---------------------------------------------------------------------------
__global__ __launch_bounds__(128) void ln_kernel(
    const float* __restrict__ in, const float* __restrict__ g,
    const float* __restrict__ b, float* __restrict__ out,
    bf16* __restrict__ oh, bf16* __restrict__ ol)
{
    const int row = blockIdx.x;
    const int t   = threadIdx.x;

    float4 v = *(const float4*)(in + (size_t)row * Dd + t * 4);
    float s  = v.x + v.y + v.z + v.w;
    float ss = v.x * v.x + v.y * v.y + v.z * v.z + v.w * v.w;

#pragma unroll
    for (int off = 16; off > 0; off >>= 1) {
        s  += __shfl_xor_sync(0xffffffffu, s, off);
        ss += __shfl_xor_sync(0xffffffffu, ss, off);
    }
    __shared__ float sm_s[4], sm_ss[4];
    if ((t & 31) == 0) { sm_s[t >> 5] = s; sm_ss[t >> 5] = ss; }
    __syncthreads();
    s  = sm_s[0] + sm_s[1] + sm_s[2] + sm_s[3];
    ss = sm_ss[0] + sm_ss[1] + sm_ss[2] + sm_ss[3];

    const float inv_n = 1.f / (float)Dd;
    float mean = s * inv_n;
    float var  = ss * inv_n - mean * mean;
    float rstd = rsqrtf(var + 1e-5f);

    float4 g4 = *(const float4*)(g + t * 4);
    float4 b4 = *(const float4*)(b + t * 4);
    float4 rr;
    rr.x = (v.x - mean) * rstd * g4.x + b4.x;
    rr.y = (v.y - mean) * rstd * g4.y + b4.y;
    rr.z = (v.z - mean) * rstd * g4.z + b4.z;
    rr.w = (v.w - mean) * rstd * g4.w + b4.w;
    *(float4*)(out + (size_t)row * Dd + t * 4) = rr;

    uint32_t h0, l0, h1, l1;
    split2(rr.x, rr.y, h0, l0);
    split2(rr.z, rr.w, h1, l1);
    *(uint2*)(oh + (size_t)row * Dd + t * 4) = make_uint2(h0, h1);
    *(uint2*)(ol + (size_t)row * Dd + t * 4) = make_uint2(l0, l1);
}

// ---------------------------------------------------------------------------
// Launcher
// ---------------------------------------------------------------------------
extern "C" void kernel_launch(void* const* d_in, const int* in_sizes, int n_in,
                              void* d_out, int out_size)
{
    const float* X     = (const float*)d_in[0];
    const float* qkv_w = (const float*)d_in[1];
    const float* qkv_b = (const float*)d_in[2];
    const float* fc_w  = (const float*)d_in[3];
    const float* fc_b  = (const float*)d_in[4];
    const float* ln1_g = (const float*)d_in[5];
    const float* ln1_b = (const float*)d_in[6];
    const float* w1    = (const float*)d_in[7];
    const float* b1    = (const float*)d_in[8];
    const float* w2    = (const float*)d_in[9];
    const float* b2    = (const float*)d_in[10];
    const float* ln2_g = (const float*)d_in[11];
    const float* ln2_b = (const float*)d_in[12];
    float* out = (float*)d_out;

    float *x, *xn, *qkv, *att;
    cudaGetSymbolAddress((void**)&x,   g_x);
    cudaGetSymbolAddress((void**)&xn,  g_xn);
    cudaGetSymbolAddress((void**)&qkv, g_qkv);
    cudaGetSymbolAddress((void**)&att, g_att);

    bf16 *Xh, *Xl, *xh, *xl, *xnh, *xnl, *ath, *atl, *h1h, *h1l;
    cudaGetSymbolAddress((void**)&Xh,  g_Xh);
    cudaGetSymbolAddress((void**)&Xl,  g_Xl);
    cudaGetSymbolAddress((void**)&xh,  g_xh);
    cudaGetSymbolAddress((void**)&xl,  g_xl);
    cudaGetSymbolAddress((void**)&xnh, g_xnh);
    cudaGetSymbolAddress((void**)&xnl, g_xnl);
    cudaGetSymbolAddress((void**)&ath, g_ath);
    cudaGetSymbolAddress((void**)&atl, g_atl);
    cudaGetSymbolAddress((void**)&h1h, g_h1h);
    cudaGetSymbolAddress((void**)&h1l, g_h1l);

    bf16 *qkvTh, *qkvTl, *fcTh, *fcTl, *w1Th, *w1Tl, *w2Th, *w2Tl;
    cudaGetSymbolAddress((void**)&qkvTh, g_qkvwTh);
    cudaGetSymbolAddress((void**)&qkvTl, g_qkvwTl);
    cudaGetSymbolAddress((void**)&fcTh,  g_fcwTh);
    cudaGetSymbolAddress((void**)&fcTl,  g_fcwTl);
    cudaGetSymbolAddress((void**)&w1Th,  g_w1Th);
    cudaGetSymbolAddress((void**)&w1Tl,  g_w1Tl);
    cudaGetSymbolAddress((void**)&w2Th,  g_w2Th);
    cudaGetSymbolAddress((void**)&w2Tl,  g_w2Tl);

    cudaFuncSetAttribute(attn_tc,
                         cudaFuncAttributeMaxDynamicSharedMemorySize, ATT_SMEM);
    cudaFuncSetAttribute(gemm_mma<0>,
                         cudaFuncAttributeMaxDynamicSharedMemorySize, GEMM_SMEM);
    cudaFuncSetAttribute(gemm_mma<FLAG_RES>,
                         cudaFuncAttributeMaxDynamicSharedMemorySize, GEMM_SMEM);
    cudaFuncSetAttribute(gemm_mma<FLAG_RELU | FLAG_OUTB>,
                         cudaFuncAttributeMaxDynamicSharedMemorySize, GEMM_SMEM);

    // One-time prep: X split + weight transpose/split
    convert_split_kernel<<<(MTOT * Dd) / 1024, 256>>>(X, Xh, Xl, MTOT * Dd);
    dim3 tb(32, 8);
    transpose_split_kernel<<<dim3(1536 / 32, 512 / 32, NBLK), tb>>>(qkv_w, qkvTh, qkvTl, 512, 1536);
    transpose_split_kernel<<<dim3(512 / 32, 512 / 32, NBLK), tb>>>(fc_w, fcTh, fcTl, 512, 512);
    transpose_split_kernel<<<dim3(1024 / 32, 512 / 32, NBLK), tb>>>(w1, w1Th, w1Tl, 512, 1024);
    transpose_split_kernel<<<dim3(512 / 32, 1024 / 32, NBLK), tb>>>(w2, w2Th, w2Tl, 1024, 512);

    for (int blk = 0; blk < NBLK; blk++) {
        const float* xin   = (blk == 0) ? X  : x;   // fp32 residual input
        const bf16*  xinh  = (blk == 0) ? Xh : xh;  // bf16 A input
        const bf16*  xinl  = (blk == 0) ? Xl : xl;

        // qkv = x @ qkv_w + qkv_b          [4096, 1536]
        gemm_mma<0><<<dim3(12, 32), 256, GEMM_SMEM>>>(
            xinh, xinl,
            qkvTh + (size_t)blk * 1536 * 512, qkvTl + (size_t)blk * 1536 * 512,
            qkv_b + (size_t)blk * 1536, nullptr, qkv, nullptr, nullptr, 512, 1536);

        // att = softmax(q k^T * scale) v   [4096, 512] (+ bf16 split)
        attn_tc<<<dim3(Ss / 128, Hh, Bb), 128, ATT_SMEM>>>(qkv, att, ath, atl);

        // x = xin + att @ fc_w + fc_b
        gemm_mma<FLAG_RES><<<dim3(4, 32), 256, GEMM_SMEM>>>(
            ath, atl,
            fcTh + (size_t)blk * 512 * 512, fcTl + (size_t)blk * 512 * 512,
            fc_b + (size_t)blk * 512, xin, x, nullptr, nullptr, 512, 512);

        // xn = ln1(x)  (bf16 split consumed by w1)
        ln_kernel<<<MTOT, 128>>>(x, ln1_g + (size_t)blk * Dd,
                                 ln1_b + (size_t)blk * Dd, xn, xnh, xnl);

        // h1 = relu(xn @ w1 + b1)          [4096, 1024]  bf16-split output only
        gemm_mma<FLAG_RELU | FLAG_OUTB><<<dim3(8, 32), 256, GEMM_SMEM>>>(
            xnh, xnl,
            w1Th + (size_t)blk * 1024 * 512, w1Tl + (size_t)blk * 1024 * 512,
            b1 + (size_t)blk * 1024, nullptr, nullptr, h1h, h1l, 512, 1024);

        // x = x + h1 @ w2 + b2
        gemm_mma<FLAG_RES><<<dim3(4, 32), 256, GEMM_SMEM>>>(
            h1h, h1l,
            w2Th + (size_t)blk * 512 * 1024, w2Tl + (size_t)blk * 512 * 1024,
            b2 + (size_t)blk * 512, x, x, nullptr, nullptr, 1024, 512);

        // x = ln2(x)   (last block writes straight to d_out)
        ln_kernel<<<MTOT, 128>>>(x, ln2_g + (size_t)blk * Dd,
                                 ln2_b + (size_t)blk * Dd,
                                 (blk == NBLK - 1) ? out : x, xh, xl);
    }
}